// round 3
// baseline (speedup 1.0000x reference)
#include <cuda_runtime.h>
#include <cuda_bf16.h>
#include <cstdint>

// Problem constants
#define BB 1024      // batch
#define UU 8         // units
#define II 512       // input dim
#define HH 512       // hidden dim
#define GN 1536      // 3*H gate dim

// Scratch for the two GEMM results (allowed: __device__ globals, no cudaMalloc)
__device__ float g_gx[(size_t)BB * UU * GN];  // 50 MB
__device__ float g_gh[(size_t)BB * UU * GN];  // 50 MB

// ---------------------------------------------------------------------------
// Tiled NT GEMM: C[b, u, g] = sum_k A[b, u, k] * W[u, g, k] + bias[u, g]
// A is [B, U, K] (row stride U*K due to unit interleave), W is [U, GN, K].
// Block tile 64(M) x 64(N), K-tile 32, 256 threads, 4x4 micro-tile per thread.
// grid: (GN/64, B/64, U*2); z selects (unit, which-matrix).
// ---------------------------------------------------------------------------
__global__ __launch_bounds__(256) void gemm_nt_kernel(
    const float* __restrict__ X,    // inputs  [B,U,I]
    const float* __restrict__ Hi,   // hidden  [B,U,H]
    const float* __restrict__ Wih,  // [U,GN,I]
    const float* __restrict__ Whh,  // [U,GN,H]
    const float* __restrict__ bih,  // [U,GN]
    const float* __restrict__ bhh)  // [U,GN]
{
    const int z = blockIdx.z;
    const int u = z >> 1;
    const int w = z & 1;

    const float* __restrict__ A    = (w == 0) ? X   : Hi;
    const float* __restrict__ Wt   = ((w == 0) ? Wih : Whh) + (size_t)u * GN * II;
    const float* __restrict__ bias = ((w == 0) ? bih : bhh) + (size_t)u * GN;
    float* __restrict__ C          = (w == 0) ? g_gx : g_gh;

    const int m0 = blockIdx.y * 64;  // batch rows
    const int n0 = blockIdx.x * 64;  // gate cols

    // Padded shared tiles: pad=65 makes the transposed stores conflict-free
    // (65 mod 32 == 1 -> bank = k + row spans all banks within a warp).
    __shared__ float As[32][65];
    __shared__ float Bs[32][65];

    const int tid = threadIdx.x;
    const int tx = tid & 15;         // 0..15 -> N micro position
    const int ty = tid >> 4;         // 0..15 -> M micro position

    // loader mapping: each thread loads 2x float4 per tile per matrix
    const int lrow = tid >> 3;        // 0..31
    const int lk   = (tid & 7) * 4;   // 0,4,...,28

    float acc[4][4];
    #pragma unroll
    for (int m = 0; m < 4; ++m)
        #pragma unroll
        for (int n = 0; n < 4; ++n) acc[m][n] = 0.0f;

    for (int k0 = 0; k0 < II; k0 += 32) {
        // A tile: 64 rows (batch) x 32 k, stored k-major (transposed)
        #pragma unroll
        for (int h = 0; h < 2; ++h) {
            const int row = lrow + h * 32;
            const float4 v = *reinterpret_cast<const float4*>(
                &A[((size_t)(m0 + row) * UU + u) * II + k0 + lk]);
            As[lk + 0][row] = v.x;
            As[lk + 1][row] = v.y;
            As[lk + 2][row] = v.z;
            As[lk + 3][row] = v.w;
        }
        // W tile: 64 rows (gates) x 32 k, stored k-major (transposed)
        #pragma unroll
        for (int h = 0; h < 2; ++h) {
            const int row = lrow + h * 32;
            const float4 v = *reinterpret_cast<const float4*>(
                &Wt[(size_t)(n0 + row) * II + k0 + lk]);
            Bs[lk + 0][row] = v.x;
            Bs[lk + 1][row] = v.y;
            Bs[lk + 2][row] = v.z;
            Bs[lk + 3][row] = v.w;
        }
        __syncthreads();

        #pragma unroll
        for (int kk = 0; kk < 32; ++kk) {
            float a[4], b[4];
            #pragma unroll
            for (int m = 0; m < 4; ++m) a[m] = As[kk][ty * 4 + m];
            #pragma unroll
            for (int n = 0; n < 4; ++n) b[n] = Bs[kk][tx * 4 + n];
            #pragma unroll
            for (int m = 0; m < 4; ++m)
                #pragma unroll
                for (int n = 0; n < 4; ++n) acc[m][n] = fmaf(a[m], b[n], acc[m][n]);
        }
        __syncthreads();
    }

    // Epilogue: add bias, write to scratch [B, U, GN]
    #pragma unroll
    for (int m = 0; m < 4; ++m) {
        const int b = m0 + ty * 4 + m;
        #pragma unroll
        for (int n = 0; n < 4; ++n) {
            const int g = n0 + tx * 4 + n;
            C[((size_t)b * UU + u) * GN + g] = acc[m][n] + bias[g];
        }
    }
}

// ---------------------------------------------------------------------------
// Elementwise GRU gate fusion:
//   r = sigmoid(xr+hr); z = sigmoid(xz+hz); n = tanh(xn + r*hn)
//   out = (1-z)*n + z*h
// ---------------------------------------------------------------------------
__global__ __launch_bounds__(256) void gru_elem_kernel(
    const float* __restrict__ Hi,   // hidden [B,U,H]
    float* __restrict__ out)        // [B,U,H]
{
    const int idx = blockIdx.x * blockDim.x + threadIdx.x;  // over B*U*H
    if (idx >= BB * UU * HH) return;

    const int j  = idx & (HH - 1);   // H = 512 (power of 2)
    const int bu = idx >> 9;         // b*U + u

    const float* __restrict__ gx = g_gx + (size_t)bu * GN;
    const float* __restrict__ gh = g_gh + (size_t)bu * GN;

    const float xr = gx[j];
    const float xz = gx[HH + j];
    const float xn = gx[2 * HH + j];
    const float hr = gh[j];
    const float hz = gh[HH + j];
    const float hn = gh[2 * HH + j];

    const float r = 1.0f / (1.0f + __expf(-(xr + hr)));
    const float z = 1.0f / (1.0f + __expf(-(xz + hz)));
    const float n = tanhf(xn + r * hn);
    const float h = Hi[idx];

    out[idx] = (1.0f - z) * n + z * h;
}

extern "C" void kernel_launch(void* const* d_in, const int* in_sizes, int n_in,
                              void* d_out, int out_size)
{
    const float* inputs = (const float*)d_in[0];  // [B,U,I]
    const float* hidden = (const float*)d_in[1];  // [B,U,H]
    const float* W_ih   = (const float*)d_in[2];  // [U,3H,I]
    const float* W_hh   = (const float*)d_in[3];  // [U,3H,H]
    const float* b_ih   = (const float*)d_in[4];  // [U,3H]
    const float* b_hh   = (const float*)d_in[5];  // [U,3H]
    float* out = (float*)d_out;                   // [B,U,H]

    // 16 GEMMs: grid.z = u*2 + which
    dim3 gemm_grid(GN / 64, BB / 64, UU * 2);     // (24, 16, 16)
    gemm_nt_kernel<<<gemm_grid, 256>>>(inputs, hidden, W_ih, W_hh, b_ih, b_hh);

    const int total = BB * UU * HH;               // 4,194,304
    gru_elem_kernel<<<total / 256, 256>>>(hidden, out);
}

// round 4
// speedup vs baseline: 1.6211x; 1.6211x over previous
#include <cuda_runtime.h>
#include <cuda_bf16.h>
#include <cstdint>

// Problem constants
#define BB 1024      // batch
#define UU 8         // units
#define II 512       // input dim
#define HH 512       // hidden dim
#define GN 1536      // 3*H gate dim

// Scratch for the two GEMM results (allowed: __device__ globals, no cudaMalloc)
__device__ float g_gx[(size_t)BB * UU * GN];  // 50 MB
__device__ float g_gh[(size_t)BB * UU * GN];  // 50 MB

// ---------------------------------------------------------------------------
// Tiled NT GEMM: C[b, u, g] = sum_k A[b, u, k] * W[u, g, k] + bias[u, g]
// A is [B, U, K] (row stride U*K due to unit interleave), W is [U, GN, K].
// Block tile 64(M) x 64(N), K-tile 32, 256 threads, 4x4 micro-tile per thread.
// grid: (GN/64, B/64, U*2); z selects (unit, which-matrix).
// ---------------------------------------------------------------------------
__global__ __launch_bounds__(256) void gemm_nt_kernel(
    const float* __restrict__ X,    // inputs  [B,U,I]
    const float* __restrict__ Hi,   // hidden  [B,U,H]
    const float* __restrict__ Wih,  // [U,GN,I]
    const float* __restrict__ Whh,  // [U,GN,H]
    const float* __restrict__ bih,  // [U,GN]
    const float* __restrict__ bhh)  // [U,GN]
{
    const int z = blockIdx.z;
    const int u = z >> 1;
    const int w = z & 1;

    const float* __restrict__ A    = (w == 0) ? X   : Hi;
    const float* __restrict__ Wt   = ((w == 0) ? Wih : Whh) + (size_t)u * GN * II;
    const float* __restrict__ bias = ((w == 0) ? bih : bhh) + (size_t)u * GN;
    float* __restrict__ C          = (w == 0) ? g_gx : g_gh;

    const int m0 = blockIdx.y * 64;  // batch rows
    const int n0 = blockIdx.x * 64;  // gate cols

    // Padded shared tiles: pad=65 makes the transposed stores conflict-free
    // (65 mod 32 == 1 -> bank = k + row spans all banks within a warp).
    __shared__ float As[32][65];
    __shared__ float Bs[32][65];

    const int tid = threadIdx.x;
    const int tx = tid & 15;         // 0..15 -> N micro position
    const int ty = tid >> 4;         // 0..15 -> M micro position

    // loader mapping: each thread loads 2x float4 per tile per matrix
    const int lrow = tid >> 3;        // 0..31
    const int lk   = (tid & 7) * 4;   // 0,4,...,28

    float acc[4][4];
    #pragma unroll
    for (int m = 0; m < 4; ++m)
        #pragma unroll
        for (int n = 0; n < 4; ++n) acc[m][n] = 0.0f;

    for (int k0 = 0; k0 < II; k0 += 32) {
        // A tile: 64 rows (batch) x 32 k, stored k-major (transposed)
        #pragma unroll
        for (int h = 0; h < 2; ++h) {
            const int row = lrow + h * 32;
            const float4 v = *reinterpret_cast<const float4*>(
                &A[((size_t)(m0 + row) * UU + u) * II + k0 + lk]);
            As[lk + 0][row] = v.x;
            As[lk + 1][row] = v.y;
            As[lk + 2][row] = v.z;
            As[lk + 3][row] = v.w;
        }
        // W tile: 64 rows (gates) x 32 k, stored k-major (transposed)
        #pragma unroll
        for (int h = 0; h < 2; ++h) {
            const int row = lrow + h * 32;
            const float4 v = *reinterpret_cast<const float4*>(
                &Wt[(size_t)(n0 + row) * II + k0 + lk]);
            Bs[lk + 0][row] = v.x;
            Bs[lk + 1][row] = v.y;
            Bs[lk + 2][row] = v.z;
            Bs[lk + 3][row] = v.w;
        }
        __syncthreads();

        #pragma unroll
        for (int kk = 0; kk < 32; ++kk) {
            float a[4], b[4];
            #pragma unroll
            for (int m = 0; m < 4; ++m) a[m] = As[kk][ty * 4 + m];
            #pragma unroll
            for (int n = 0; n < 4; ++n) b[n] = Bs[kk][tx * 4 + n];
            #pragma unroll
            for (int m = 0; m < 4; ++m)
                #pragma unroll
                for (int n = 0; n < 4; ++n) acc[m][n] = fmaf(a[m], b[n], acc[m][n]);
        }
        __syncthreads();
    }

    // Epilogue: add bias, write to scratch [B, U, GN]
    #pragma unroll
    for (int m = 0; m < 4; ++m) {
        const int b = m0 + ty * 4 + m;
        #pragma unroll
        for (int n = 0; n < 4; ++n) {
            const int g = n0 + tx * 4 + n;
            C[((size_t)b * UU + u) * GN + g] = acc[m][n] + bias[g];
        }
    }
}

// ---------------------------------------------------------------------------
// Elementwise GRU gate fusion:
//   r = sigmoid(xr+hr); z = sigmoid(xz+hz); n = tanh(xn + r*hn)
//   out = (1-z)*n + z*h
// ---------------------------------------------------------------------------
__global__ __launch_bounds__(256) void gru_elem_kernel(
    const float* __restrict__ Hi,   // hidden [B,U,H]
    float* __restrict__ out)        // [B,U,H]
{
    const int idx = blockIdx.x * blockDim.x + threadIdx.x;  // over B*U*H
    if (idx >= BB * UU * HH) return;

    const int j  = idx & (HH - 1);   // H = 512 (power of 2)
    const int bu = idx >> 9;         // b*U + u

    const float* __restrict__ gx = g_gx + (size_t)bu * GN;
    const float* __restrict__ gh = g_gh + (size_t)bu * GN;

    const float xr = gx[j];
    const float xz = gx[HH + j];
    const float xn = gx[2 * HH + j];
    const float hr = gh[j];
    const float hz = gh[HH + j];
    const float hn = gh[2 * HH + j];

    const float r = 1.0f / (1.0f + __expf(-(xr + hr)));
    const float z = 1.0f / (1.0f + __expf(-(xz + hz)));
    const float n = tanhf(xn + r * hn);
    const float h = Hi[idx];

    out[idx] = (1.0f - z) * n + z * h;
}

extern "C" void kernel_launch(void* const* d_in, const int* in_sizes, int n_in,
                              void* d_out, int out_size)
{
    const float* inputs = (const float*)d_in[0];  // [B,U,I]
    const float* hidden = (const float*)d_in[1];  // [B,U,H]
    const float* W_ih   = (const float*)d_in[2];  // [U,3H,I]
    const float* W_hh   = (const float*)d_in[3];  // [U,3H,H]
    const float* b_ih   = (const float*)d_in[4];  // [U,3H]
    const float* b_hh   = (const float*)d_in[5];  // [U,3H]
    float* out = (float*)d_out;                   // [B,U,H]

    // 16 GEMMs: grid.z = u*2 + which
    dim3 gemm_grid(GN / 64, BB / 64, UU * 2);     // (24, 16, 16)
    gemm_nt_kernel<<<gemm_grid, 256>>>(inputs, hidden, W_ih, W_hh, b_ih, b_hh);

    const int total = BB * UU * HH;               // 4,194,304
    gru_elem_kernel<<<total / 256, 256>>>(hidden, out);
}

// round 6
// speedup vs baseline: 4.3336x; 2.6732x over previous
#include <cuda_runtime.h>
#include <cuda_bf16.h>
#include <cstdint>

// Problem constants
#define BB 1024
#define UU 8
#define II 512
#define HH 512
#define GN 1536      // 3*H
#define K3 1536      // split-bf16 widened K (3 * 512)

// GEMM tiling
#define TM 128
#define TN 256
#define KC 64                 // bf16 k per stage (128 B rows)
#define NSTEPS (K3 / KC)      // 24
#define STAGES 4
#define STAGE_BYTES (TM * 128 + TN * 128)     // 16K + 32K = 48K
#define SMEM_BYTES (STAGES * STAGE_BYTES)     // 192 KB

// ---------------------------------------------------------------------------
// Device scratch
// ---------------------------------------------------------------------------
__device__ __nv_bfloat16 g_xc  [(size_t)BB * UU * K3];   // X split  [hi|lo|hi]
__device__ __nv_bfloat16 g_hc  [(size_t)BB * UU * K3];   // H split
__device__ __nv_bfloat16 g_wih [(size_t)UU * GN * K3];   // Wih split [hi|hi|lo]
__device__ __nv_bfloat16 g_whh [(size_t)UU * GN * K3];   // Whh split
__device__ float g_gx[(size_t)BB * UU * GN];
__device__ float g_gh[(size_t)BB * UU * GN];

// ---------------------------------------------------------------------------
// helpers
// ---------------------------------------------------------------------------
__device__ __forceinline__ uint32_t smem_u32(const void* p) {
    return (uint32_t)__cvta_generic_to_shared(p);
}
__device__ __forceinline__ uint32_t sw128(uint32_t off) {
    return off ^ ((off >> 3) & 0x70);
}

#define CP_ASYNC16(dst, src) \
    asm volatile("cp.async.cg.shared.global [%0], [%1], 16;" :: "r"(dst), "l"(src))
#define CP_COMMIT() asm volatile("cp.async.commit_group;" ::: "memory")
#define CP_WAIT2()  asm volatile("cp.async.wait_group 2;" ::: "memory")

#define LDMATRIX_X4(r0, r1, r2, r3, addr) \
    asm volatile("ldmatrix.sync.aligned.m8n8.x4.shared.b16 {%0,%1,%2,%3}, [%4];" \
                 : "=r"(r0), "=r"(r1), "=r"(r2), "=r"(r3) : "r"(addr))

#define MMA_16816(c, a, b0, b1) \
    asm volatile("mma.sync.aligned.m16n8k16.row.col.f32.bf16.bf16.f32 " \
                 "{%0,%1,%2,%3}, {%4,%5,%6,%7}, {%8,%9}, {%0,%1,%2,%3};" \
                 : "+f"((c)[0]), "+f"((c)[1]), "+f"((c)[2]), "+f"((c)[3]) \
                 : "r"((a)[0]), "r"((a)[1]), "r"((a)[2]), "r"((a)[3]), \
                   "r"(b0), "r"(b1))

// ---------------------------------------------------------------------------
// fp32 -> split bf16 conversion.
// wmode=0 (activations): [hi | lo | hi]   wmode=1 (weights): [hi | hi | lo]
// ---------------------------------------------------------------------------
__global__ __launch_bounds__(256) void cvt_kernel(
    const float* __restrict__ src, __nv_bfloat16* __restrict__ dst,
    int total, int wmode)
{
    const int i = blockIdx.x * blockDim.x + threadIdx.x;
    if (i >= total) return;
    const int row = i >> 9;          // K=512
    const int k   = i & 511;
    const float a = src[i];
    const __nv_bfloat16 hi = __float2bfloat16(a);
    const __nv_bfloat16 lo = __float2bfloat16(a - __bfloat162float(hi));
    const size_t base = (size_t)row * K3;
    dst[base + k]        = hi;
    dst[base + 512 + k]  = wmode ? hi : lo;
    dst[base + 1024 + k] = wmode ? lo : hi;
}

// ---------------------------------------------------------------------------
// mma.sync bf16 GEMM: C[m0+r, u, n0+c] = sum_k A'[row,k] * W'[col,k]
// CTA tile 128x256, 8 warps (2M x 4N), warp tile 64x64.
// grid = (GN/TN=6, BB/TM=8, 16); z = u*2 + which
// ---------------------------------------------------------------------------
__global__ __launch_bounds__(256, 1) void gemm_mmasync_kernel()
{
    extern __shared__ __align__(1024) char smem[];

    const int z = blockIdx.z;
    const int u = z >> 1;
    const int w = z & 1;
    const __nv_bfloat16* __restrict__ Asrc = w ? g_hc : g_xc;
    const __nv_bfloat16* __restrict__ Wsrc = (w ? g_whh : g_wih) + (size_t)u * GN * K3;
    float* __restrict__ C = w ? g_gh : g_gx;

    const int m0 = blockIdx.y * TM;
    const int n0 = blockIdx.x * TN;

    const int tid  = threadIdx.x;
    const int wid  = tid >> 5;
    const int lane = tid & 31;
    const int wm   = wid & 1;        // warp M position (0..1)
    const int wn   = wid >> 1;       // warp N position (0..3)

    const uint32_t sb = smem_u32(smem);

    // ---------- loader precompute (per-thread fixed offsets) ----------
    const __nv_bfloat16* a_base = Asrc + ((size_t)m0 * UU + u) * K3;
    const __nv_bfloat16* b_base = Wsrc + (size_t)n0 * K3;

    uint32_t a_off[4];  const __nv_bfloat16* a_src[4];
    #pragma unroll
    for (int j = 0; j < 4; ++j) {
        const int idx = tid + 256 * j;          // 0..1023
        const int r = idx >> 3, v = idx & 7;
        a_off[j] = sw128((uint32_t)(r * 128 + v * 16));
        a_src[j] = a_base + (size_t)r * (UU * K3) + v * 8;
    }
    uint32_t b_off[8];  const __nv_bfloat16* b_src[8];
    #pragma unroll
    for (int j = 0; j < 8; ++j) {
        const int idx = tid + 256 * j;          // 0..2047
        const int r = idx >> 3, v = idx & 7;
        b_off[j] = sw128((uint32_t)(r * 128 + v * 16));
        b_src[j] = b_base + (size_t)r * K3 + v * 8;
    }

    // ---------- fragment address precompute ----------
    // A ldmatrix.x4 per (mt, kk): row = wm*64 + mt*16 + (lane&15),
    //                             colB = kk*32 + (lane>>4)*16
    uint32_t a_frag_off[4];   // per mt, kk=0 base; add kk*32 xor'd? swizzle is per-offset:
    // swizzle depends on full offset; precompute raw and apply sw128 at use.
    const uint32_t a_row = (uint32_t)((lane & 15));
    const uint32_t a_colB = (uint32_t)((lane >> 4) << 4);
    #pragma unroll
    for (int mt = 0; mt < 4; ++mt)
        a_frag_off[mt] = (uint32_t)((wm * 64 + mt * 16 + a_row) * 128) + a_colB;

    // B ldmatrix.x4 per (nb, kk): nrow = wn*64 + nb*16 + ((lane&7) | ((lane>>4)<<3)),
    //                             colB = kk*32 + ((lane>>3)&1)*16
    uint32_t b_frag_off[4];
    const uint32_t b_row = (uint32_t)((lane & 7) | ((lane >> 4) << 3));
    const uint32_t b_colB = (uint32_t)(((lane >> 3) & 1) << 4);
    #pragma unroll
    for (int nb = 0; nb < 4; ++nb)
        b_frag_off[nb] = (uint32_t)((wn * 64 + nb * 16 + b_row) * 128) + b_colB;

    float acc[4][8][4];
    #pragma unroll
    for (int mt = 0; mt < 4; ++mt)
        #pragma unroll
        for (int nt = 0; nt < 8; ++nt)
            #pragma unroll
            for (int q = 0; q < 4; ++q) acc[mt][nt][q] = 0.0f;

    // ---------- stage load helper ----------
    auto load_stage = [&](int st) {
        const uint32_t abase = sb + (uint32_t)st * STAGE_BYTES;
        const uint32_t bbase = abase + TM * 128;
        #pragma unroll
        for (int j = 0; j < 4; ++j) {
            CP_ASYNC16(abase + a_off[j], a_src[j]);
            a_src[j] += KC;
        }
        #pragma unroll
        for (int j = 0; j < 8; ++j) {
            CP_ASYNC16(bbase + b_off[j], b_src[j]);
            b_src[j] += KC;
        }
    };

    // prologue: stages 0..2
    #pragma unroll
    for (int p = 0; p < STAGES - 1; ++p) { load_stage(p); CP_COMMIT(); }
    CP_WAIT2();
    __syncthreads();

    for (int s = 0; s < NSTEPS; ++s) {
        if (s + STAGES - 1 < NSTEPS) load_stage((s + STAGES - 1) % STAGES);
        CP_COMMIT();

        const int st = s % STAGES;
        const uint32_t As = sb + (uint32_t)st * STAGE_BYTES;
        const uint32_t Bs = As + TM * 128;

        #pragma unroll
        for (int kk = 0; kk < 4; ++kk) {
            uint32_t a[4][4];
            #pragma unroll
            for (int mt = 0; mt < 4; ++mt) {
                const uint32_t addr = As + sw128(a_frag_off[mt] + kk * 32);
                LDMATRIX_X4(a[mt][0], a[mt][1], a[mt][2], a[mt][3], addr);
            }
            uint32_t b[4][4];
            #pragma unroll
            for (int nb = 0; nb < 4; ++nb) {
                const uint32_t addr = Bs + sw128(b_frag_off[nb] + kk * 32);
                LDMATRIX_X4(b[nb][0], b[nb][1], b[nb][2], b[nb][3], addr);
            }
            #pragma unroll
            for (int mt = 0; mt < 4; ++mt) {
                #pragma unroll
                for (int nb = 0; nb < 4; ++nb) {
                    MMA_16816(acc[mt][2 * nb],     a[mt], b[nb][0], b[nb][1]);
                    MMA_16816(acc[mt][2 * nb + 1], a[mt], b[nb][2], b[nb][3]);
                }
            }
        }

        CP_WAIT2();
        __syncthreads();
    }

    // ---------- epilogue: regs -> global ----------
    const int g = lane >> 2;         // 0..7
    const int d = lane & 3;          // 0..3
    #pragma unroll
    for (int mt = 0; mt < 4; ++mt) {
        const int row0 = m0 + wm * 64 + mt * 16 + g;
        float* __restrict__ c0 = C + ((size_t)row0 * UU + u) * GN;
        float* __restrict__ c1 = C + ((size_t)(row0 + 8) * UU + u) * GN;
        #pragma unroll
        for (int nt = 0; nt < 8; ++nt) {
            const int col = n0 + wn * 64 + nt * 8 + d * 2;
            float2 v0 = {acc[mt][nt][0], acc[mt][nt][1]};
            float2 v1 = {acc[mt][nt][2], acc[mt][nt][3]};
            *reinterpret_cast<float2*>(c0 + col) = v0;
            *reinterpret_cast<float2*>(c1 + col) = v1;
        }
    }
}

// ---------------------------------------------------------------------------
// Elementwise GRU gates (+bias fold)
// ---------------------------------------------------------------------------
__global__ __launch_bounds__(256) void gru_elem_kernel(
    const float* __restrict__ Hi,
    const float* __restrict__ bih,
    const float* __restrict__ bhh,
    float* __restrict__ out)
{
    const int idx = blockIdx.x * blockDim.x + threadIdx.x;
    if (idx >= BB * UU * HH) return;

    const int j  = idx & (HH - 1);
    const int bu = idx >> 9;
    const int u  = bu & (UU - 1);

    const float* __restrict__ gx = g_gx + (size_t)bu * GN;
    const float* __restrict__ gh = g_gh + (size_t)bu * GN;
    const float* __restrict__ bi = bih + u * GN;
    const float* __restrict__ bh = bhh + u * GN;

    const float xr = gx[j]          + bi[j];
    const float xz = gx[HH + j]     + bi[HH + j];
    const float xn = gx[2 * HH + j] + bi[2 * HH + j];
    const float hr = gh[j]          + bh[j];
    const float hz = gh[HH + j]     + bh[HH + j];
    const float hn = gh[2 * HH + j] + bh[2 * HH + j];

    const float r = 1.0f / (1.0f + __expf(-(xr + hr)));
    const float z = 1.0f / (1.0f + __expf(-(xz + hz)));
    const float n = tanhf(xn + r * hn);
    const float h = Hi[idx];

    out[idx] = (1.0f - z) * n + z * h;
}

// ---------------------------------------------------------------------------
extern "C" void kernel_launch(void* const* d_in, const int* in_sizes, int n_in,
                              void* d_out, int out_size)
{
    const float* inputs = (const float*)d_in[0];  // [B,U,I]
    const float* hidden = (const float*)d_in[1];  // [B,U,H]
    const float* W_ih   = (const float*)d_in[2];  // [U,3H,I]
    const float* W_hh   = (const float*)d_in[3];  // [U,3H,H]
    const float* b_ih   = (const float*)d_in[4];  // [U,3H]
    const float* b_hh   = (const float*)d_in[5];  // [U,3H]
    float* out = (float*)d_out;                   // [B,U,H]

    cudaFuncSetAttribute(gemm_mmasync_kernel,
                         cudaFuncAttributeMaxDynamicSharedMemorySize, SMEM_BYTES);

    __nv_bfloat16 *xc, *hc, *wih, *whh;
    cudaGetSymbolAddress((void**)&xc,  g_xc);
    cudaGetSymbolAddress((void**)&hc,  g_hc);
    cudaGetSymbolAddress((void**)&wih, g_wih);
    cudaGetSymbolAddress((void**)&whh, g_whh);

    const int act_total = BB * UU * II;      // 4,194,304
    const int w_total   = UU * GN * II;      // 6,291,456
    cvt_kernel<<<(act_total + 255) / 256, 256>>>(inputs, xc,  act_total, 0);
    cvt_kernel<<<(act_total + 255) / 256, 256>>>(hidden, hc,  act_total, 0);
    cvt_kernel<<<(w_total   + 255) / 256, 256>>>(W_ih,   wih, w_total,   1);
    cvt_kernel<<<(w_total   + 255) / 256, 256>>>(W_hh,   whh, w_total,   1);

    dim3 gemm_grid(GN / TN, BB / TM, UU * 2);   // (6, 8, 16)
    gemm_mmasync_kernel<<<gemm_grid, 256, SMEM_BYTES>>>();

    const int total = BB * UU * HH;
    gru_elem_kernel<<<total / 256, 256>>>(hidden, b_ih, b_hh, out);
}

// round 7
// speedup vs baseline: 4.9473x; 1.1416x over previous
#include <cuda_runtime.h>
#include <cuda_bf16.h>
#include <cstdint>

// Problem constants
#define BB 1024
#define UU 8
#define II 512
#define HH 512
#define GN 1536      // 3*H
#define K3 1536      // split-bf16 widened K (3 * 512)

// GEMM tiling
#define TM 128
#define TN 256
#define KC 64                 // bf16 k per stage (128 B rows)
#define NSTEPS (K3 / KC)      // 24
#define STAGES 4
#define STAGE_BYTES (TM * 128 + TN * 128)     // 16K + 32K = 48K
#define SMEM_BYTES (STAGES * STAGE_BYTES)     // 192 KB

// ---------------------------------------------------------------------------
// Device scratch
// ---------------------------------------------------------------------------
// Activations de-interleaved: [U][B][K3] so GEMM A rows are contiguous (3 KB stride)
__device__ __nv_bfloat16 g_xc  [(size_t)UU * BB * K3];   // X split  [hi|lo|hi]
__device__ __nv_bfloat16 g_hc  [(size_t)UU * BB * K3];   // H split
__device__ __nv_bfloat16 g_wih [(size_t)UU * GN * K3];   // Wih split [hi|hi|lo]
__device__ __nv_bfloat16 g_whh [(size_t)UU * GN * K3];   // Whh split
__device__ float g_gx[(size_t)BB * UU * GN];             // [B][U][GN]
__device__ float g_gh[(size_t)BB * UU * GN];

// ---------------------------------------------------------------------------
// helpers
// ---------------------------------------------------------------------------
__device__ __forceinline__ uint32_t smem_u32(const void* p) {
    return (uint32_t)__cvta_generic_to_shared(p);
}
__device__ __forceinline__ uint32_t sw128(uint32_t off) {
    return off ^ ((off >> 3) & 0x70);
}

#define CP_ASYNC16(dst, src) \
    asm volatile("cp.async.cg.shared.global [%0], [%1], 16;" :: "r"(dst), "l"(src))
#define CP_COMMIT() asm volatile("cp.async.commit_group;" ::: "memory")
#define CP_WAIT2()  asm volatile("cp.async.wait_group 2;" ::: "memory")

#define LDMATRIX_X4(r0, r1, r2, r3, addr) \
    asm volatile("ldmatrix.sync.aligned.m8n8.x4.shared.b16 {%0,%1,%2,%3}, [%4];" \
                 : "=r"(r0), "=r"(r1), "=r"(r2), "=r"(r3) : "r"(addr))

#define MMA_16816(c, a, b0, b1) \
    asm volatile("mma.sync.aligned.m16n8k16.row.col.f32.bf16.bf16.f32 " \
                 "{%0,%1,%2,%3}, {%4,%5,%6,%7}, {%8,%9}, {%0,%1,%2,%3};" \
                 : "+f"((c)[0]), "+f"((c)[1]), "+f"((c)[2]), "+f"((c)[3]) \
                 : "r"((a)[0]), "r"((a)[1]), "r"((a)[2]), "r"((a)[3]), \
                   "r"(b0), "r"(b1))

// ---------------------------------------------------------------------------
// fp32 -> split bf16 conversion, 4 elems/thread (float4).
// wmode=0 (activations): dst layout [U][B][K3], blocks [hi | lo | hi]
// wmode=1 (weights):     dst layout unchanged,  blocks [hi | hi | lo]
// so that A'.B' = ahi*bhi + alo*bhi + ahi*blo
// ---------------------------------------------------------------------------
__global__ __launch_bounds__(256) void cvt_kernel(
    const float4* __restrict__ src, __nv_bfloat16* __restrict__ dst,
    int total4, int wmode)
{
    const int i = blockIdx.x * blockDim.x + threadIdx.x;   // over total/4
    if (i >= total4) return;

    const int k4  = i & 127;          // 512/4 = 128 float4 per row
    const int row = i >> 7;

    const float4 v = src[i];

    const __nv_bfloat16 hx = __float2bfloat16(v.x);
    const __nv_bfloat16 hy = __float2bfloat16(v.y);
    const __nv_bfloat16 hz = __float2bfloat16(v.z);
    const __nv_bfloat16 hw = __float2bfloat16(v.w);
    const __nv_bfloat16 lx = __float2bfloat16(v.x - __bfloat162float(hx));
    const __nv_bfloat16 ly = __float2bfloat16(v.y - __bfloat162float(hy));
    const __nv_bfloat16 lz = __float2bfloat16(v.z - __bfloat162float(hz));
    const __nv_bfloat16 lw = __float2bfloat16(v.w - __bfloat162float(hw));

    uint2 hpack, lpack;
    {
        __nv_bfloat162 h01 = __halves2bfloat162(hx, hy);
        __nv_bfloat162 h23 = __halves2bfloat162(hz, hw);
        __nv_bfloat162 l01 = __halves2bfloat162(lx, ly);
        __nv_bfloat162 l23 = __halves2bfloat162(lz, lw);
        hpack.x = *reinterpret_cast<uint32_t*>(&h01);
        hpack.y = *reinterpret_cast<uint32_t*>(&h23);
        lpack.x = *reinterpret_cast<uint32_t*>(&l01);
        lpack.y = *reinterpret_cast<uint32_t*>(&l23);
    }

    // destination row: activations de-interleave [B][U] -> [U][B]
    const int drow = wmode ? row : ((row & 7) * BB + (row >> 3));
    uint2* __restrict__ base = reinterpret_cast<uint2*>(dst + (size_t)drow * K3) + k4;

    base[0]       = hpack;                     // k block 0: hi
    base[128]     = wmode ? hpack : lpack;     // k block 1 (offset 512 elems)
    base[256]     = wmode ? lpack : hpack;     // k block 2 (offset 1024 elems)
}

// ---------------------------------------------------------------------------
// mma.sync bf16 GEMM: C[m0+r, u, n0+c] = sum_k A'[u, row, k] * W'[u, col, k]
// CTA tile 128x256, 8 warps (2M x 4N), warp tile 64x64.
// grid = (GN/TN=6, BB/TM=8, 16); z = u*2 + which
// ---------------------------------------------------------------------------
__global__ __launch_bounds__(256, 1) void gemm_mmasync_kernel()
{
    extern __shared__ __align__(1024) char smem[];

    const int z = blockIdx.z;
    const int u = z >> 1;
    const int w = z & 1;
    const __nv_bfloat16* __restrict__ Asrc = w ? g_hc : g_xc;
    const __nv_bfloat16* __restrict__ Wsrc = (w ? g_whh : g_wih) + (size_t)u * GN * K3;
    float* __restrict__ C = w ? g_gh : g_gx;

    const int m0 = blockIdx.y * TM;
    const int n0 = blockIdx.x * TN;

    const int tid  = threadIdx.x;
    const int wid  = tid >> 5;
    const int lane = tid & 31;
    const int wm   = wid & 1;        // warp M position (0..1)
    const int wn   = wid >> 1;       // warp N position (0..3)

    const uint32_t sb = smem_u32(smem);

    // ---------- loader precompute (per-thread fixed offsets) ----------
    const __nv_bfloat16* a_base = Asrc + ((size_t)u * BB + m0) * K3;   // rows stride K3
    const __nv_bfloat16* b_base = Wsrc + (size_t)n0 * K3;

    uint32_t a_off[4];  const __nv_bfloat16* a_src[4];
    #pragma unroll
    for (int j = 0; j < 4; ++j) {
        const int idx = tid + 256 * j;          // 0..1023
        const int r = idx >> 3, v = idx & 7;
        a_off[j] = sw128((uint32_t)(r * 128 + v * 16));
        a_src[j] = a_base + (size_t)r * K3 + v * 8;
    }
    uint32_t b_off[8];  const __nv_bfloat16* b_src[8];
    #pragma unroll
    for (int j = 0; j < 8; ++j) {
        const int idx = tid + 256 * j;          // 0..2047
        const int r = idx >> 3, v = idx & 7;
        b_off[j] = sw128((uint32_t)(r * 128 + v * 16));
        b_src[j] = b_base + (size_t)r * K3 + v * 8;
    }

    // ---------- fragment address precompute ----------
    const uint32_t a_row  = (uint32_t)(lane & 15);
    const uint32_t a_colB = (uint32_t)((lane >> 4) << 4);
    uint32_t a_frag_off[4];
    #pragma unroll
    for (int mt = 0; mt < 4; ++mt)
        a_frag_off[mt] = (uint32_t)((wm * 64 + mt * 16 + a_row) * 128) + a_colB;

    const uint32_t b_row  = (uint32_t)((lane & 7) | ((lane >> 4) << 3));
    const uint32_t b_colB = (uint32_t)(((lane >> 3) & 1) << 4);
    uint32_t b_frag_off[4];
    #pragma unroll
    for (int nb = 0; nb < 4; ++nb)
        b_frag_off[nb] = (uint32_t)((wn * 64 + nb * 16 + b_row) * 128) + b_colB;

    float acc[4][8][4];
    #pragma unroll
    for (int mt = 0; mt < 4; ++mt)
        #pragma unroll
        for (int nt = 0; nt < 8; ++nt)
            #pragma unroll
            for (int q = 0; q < 4; ++q) acc[mt][nt][q] = 0.0f;

    // ---------- stage load helper ----------
    auto load_stage = [&](int st) {
        const uint32_t abase = sb + (uint32_t)st * STAGE_BYTES;
        const uint32_t bbase = abase + TM * 128;
        #pragma unroll
        for (int j = 0; j < 4; ++j) {
            CP_ASYNC16(abase + a_off[j], a_src[j]);
            a_src[j] += KC;
        }
        #pragma unroll
        for (int j = 0; j < 8; ++j) {
            CP_ASYNC16(bbase + b_off[j], b_src[j]);
            b_src[j] += KC;
        }
    };

    // prologue: stages 0..2
    #pragma unroll
    for (int p = 0; p < STAGES - 1; ++p) { load_stage(p); CP_COMMIT(); }
    CP_WAIT2();
    __syncthreads();

    for (int s = 0; s < NSTEPS; ++s) {
        if (s + STAGES - 1 < NSTEPS) load_stage((s + STAGES - 1) % STAGES);
        CP_COMMIT();

        const int st = s % STAGES;
        const uint32_t As = sb + (uint32_t)st * STAGE_BYTES;
        const uint32_t Bs = As + TM * 128;

        #pragma unroll
        for (int kk = 0; kk < 4; ++kk) {
            uint32_t a[4][4];
            #pragma unroll
            for (int mt = 0; mt < 4; ++mt) {
                const uint32_t addr = As + sw128(a_frag_off[mt] + kk * 32);
                LDMATRIX_X4(a[mt][0], a[mt][1], a[mt][2], a[mt][3], addr);
            }
            uint32_t b[4][4];
            #pragma unroll
            for (int nb = 0; nb < 4; ++nb) {
                const uint32_t addr = Bs + sw128(b_frag_off[nb] + kk * 32);
                LDMATRIX_X4(b[nb][0], b[nb][1], b[nb][2], b[nb][3], addr);
            }
            #pragma unroll
            for (int mt = 0; mt < 4; ++mt) {
                #pragma unroll
                for (int nb = 0; nb < 4; ++nb) {
                    MMA_16816(acc[mt][2 * nb],     a[mt], b[nb][0], b[nb][1]);
                    MMA_16816(acc[mt][2 * nb + 1], a[mt], b[nb][2], b[nb][3]);
                }
            }
        }

        CP_WAIT2();
        __syncthreads();
    }

    // ---------- epilogue: regs -> global ([B][U][GN]) ----------
    const int g = lane >> 2;         // 0..7
    const int d = lane & 3;          // 0..3
    #pragma unroll
    for (int mt = 0; mt < 4; ++mt) {
        const int row0 = m0 + wm * 64 + mt * 16 + g;
        float* __restrict__ c0 = C + ((size_t)row0 * UU + u) * GN;
        float* __restrict__ c1 = C + ((size_t)(row0 + 8) * UU + u) * GN;
        #pragma unroll
        for (int nt = 0; nt < 8; ++nt) {
            const int col = n0 + wn * 64 + nt * 8 + d * 2;
            float2 v0 = {acc[mt][nt][0], acc[mt][nt][1]};
            float2 v1 = {acc[mt][nt][2], acc[mt][nt][3]};
            *reinterpret_cast<float2*>(c0 + col) = v0;
            *reinterpret_cast<float2*>(c1 + col) = v1;
        }
    }
}

// ---------------------------------------------------------------------------
// Elementwise GRU gates (+bias fold), 4 outputs/thread (float4)
// ---------------------------------------------------------------------------
__global__ __launch_bounds__(256) void gru_elem_kernel(
    const float4* __restrict__ Hi,    // hidden [B][U][H] as float4
    const float* __restrict__ bih,
    const float* __restrict__ bhh,
    float4* __restrict__ out)
{
    const int i = blockIdx.x * blockDim.x + threadIdx.x;   // over B*U*H/4
    if (i >= BB * UU * HH / 4) return;

    const int j4 = i & 127;          // H/4 = 128
    const int bu = i >> 7;
    const int u  = bu & (UU - 1);

    const float4* __restrict__ gx = reinterpret_cast<const float4*>(g_gx + (size_t)bu * GN) + j4;
    const float4* __restrict__ gh = reinterpret_cast<const float4*>(g_gh + (size_t)bu * GN) + j4;
    const float4* __restrict__ bi = reinterpret_cast<const float4*>(bih + u * GN) + j4;
    const float4* __restrict__ bh = reinterpret_cast<const float4*>(bhh + u * GN) + j4;

    // three gate blocks at float4-offsets 0, 128, 256
    const float4 xr = gx[0],   hr = gh[0];
    const float4 xz = gx[128], hz = gh[128];
    const float4 xn = gx[256], hn = gh[256];
    const float4 br = bi[0],   cr = bh[0];
    const float4 bz = bi[128], cz = bh[128];
    const float4 bn = bi[256], cn = bh[256];
    const float4 h  = Hi[i];

    float4 o;
    {
        const float r = 1.0f / (1.0f + __expf(-(xr.x + br.x + hr.x + cr.x)));
        const float zz = 1.0f / (1.0f + __expf(-(xz.x + bz.x + hz.x + cz.x)));
        const float n = tanhf(xn.x + bn.x + r * (hn.x + cn.x));
        o.x = (1.0f - zz) * n + zz * h.x;
    }
    {
        const float r = 1.0f / (1.0f + __expf(-(xr.y + br.y + hr.y + cr.y)));
        const float zz = 1.0f / (1.0f + __expf(-(xz.y + bz.y + hz.y + cz.y)));
        const float n = tanhf(xn.y + bn.y + r * (hn.y + cn.y));
        o.y = (1.0f - zz) * n + zz * h.y;
    }
    {
        const float r = 1.0f / (1.0f + __expf(-(xr.z + br.z + hr.z + cr.z)));
        const float zz = 1.0f / (1.0f + __expf(-(xz.z + bz.z + hz.z + cz.z)));
        const float n = tanhf(xn.z + bn.z + r * (hn.z + cn.z));
        o.z = (1.0f - zz) * n + zz * h.z;
    }
    {
        const float r = 1.0f / (1.0f + __expf(-(xr.w + br.w + hr.w + cr.w)));
        const float zz = 1.0f / (1.0f + __expf(-(xz.w + bz.w + hz.w + cz.w)));
        const float n = tanhf(xn.w + bn.w + r * (hn.w + cn.w));
        o.w = (1.0f - zz) * n + zz * h.w;
    }
    out[i] = o;
}

// ---------------------------------------------------------------------------
extern "C" void kernel_launch(void* const* d_in, const int* in_sizes, int n_in,
                              void* d_out, int out_size)
{
    const float* inputs = (const float*)d_in[0];  // [B,U,I]
    const float* hidden = (const float*)d_in[1];  // [B,U,H]
    const float* W_ih   = (const float*)d_in[2];  // [U,3H,I]
    const float* W_hh   = (const float*)d_in[3];  // [U,3H,H]
    const float* b_ih   = (const float*)d_in[4];  // [U,3H]
    const float* b_hh   = (const float*)d_in[5];  // [U,3H]
    float* out = (float*)d_out;                   // [B,U,H]

    cudaFuncSetAttribute(gemm_mmasync_kernel,
                         cudaFuncAttributeMaxDynamicSharedMemorySize, SMEM_BYTES);

    __nv_bfloat16 *xc, *hc, *wih, *whh;
    cudaGetSymbolAddress((void**)&xc,  g_xc);
    cudaGetSymbolAddress((void**)&hc,  g_hc);
    cudaGetSymbolAddress((void**)&wih, g_wih);
    cudaGetSymbolAddress((void**)&whh, g_whh);

    const int act4 = BB * UU * II / 4;      // 1,048,576
    const int w4   = UU * GN * II / 4;      // 1,572,864
    cvt_kernel<<<(act4 + 255) / 256, 256>>>((const float4*)inputs, xc,  act4, 0);
    cvt_kernel<<<(act4 + 255) / 256, 256>>>((const float4*)hidden, hc,  act4, 0);
    cvt_kernel<<<(w4   + 255) / 256, 256>>>((const float4*)W_ih,   wih, w4,   1);
    cvt_kernel<<<(w4   + 255) / 256, 256>>>((const float4*)W_hh,   whh, w4,   1);

    dim3 gemm_grid(GN / TN, BB / TM, UU * 2);   // (6, 8, 16)
    gemm_mmasync_kernel<<<gemm_grid, 256, SMEM_BYTES>>>();

    const int total4 = BB * UU * HH / 4;
    gru_elem_kernel<<<(total4 + 255) / 256, 256>>>(
        (const float4*)hidden, b_ih, b_hh, (float4*)out);
}

// round 8
// speedup vs baseline: 5.3380x; 1.0790x over previous
#include <cuda_runtime.h>
#include <cuda_bf16.h>
#include <cstdint>

// Problem constants
#define BB 1024
#define UU 8
#define II 512
#define HH 512
#define GN 1536      // 3*H
#define K2 1024      // scratch K: [hi(512) | lo(512)]
#define KREAL 512

// GEMM tiling
#define TM 128
#define TN 256
#define KC 64                 // bf16 k per stage (128 B rows)
#define NSTEPS (KREAL / KC)   // 8
#define STAGES 2
// per stage: Ahi 16K, Alo 16K, Bhi 32K, Blo 32K
#define ST_AHI 0
#define ST_ALO 16384
#define ST_BHI 32768
#define ST_BLO 65536
#define STAGE_BYTES 98304
#define SMEM_BYTES (STAGES * STAGE_BYTES)     // 192 KB

// ---------------------------------------------------------------------------
// Device scratch
// ---------------------------------------------------------------------------
// Activations de-interleaved: [U][B][K2] (hi at k, lo at k+512)
__device__ __nv_bfloat16 g_xc  [(size_t)UU * BB * K2];
__device__ __nv_bfloat16 g_hc  [(size_t)UU * BB * K2];
__device__ __nv_bfloat16 g_wih [(size_t)UU * GN * K2];   // [U][GN][K2]
__device__ __nv_bfloat16 g_whh [(size_t)UU * GN * K2];
__device__ float g_gx[(size_t)BB * UU * GN];             // [B][U][GN]
__device__ float g_gh[(size_t)BB * UU * GN];

// ---------------------------------------------------------------------------
// helpers
// ---------------------------------------------------------------------------
__device__ __forceinline__ uint32_t smem_u32(const void* p) {
    return (uint32_t)__cvta_generic_to_shared(p);
}
__device__ __forceinline__ uint32_t sw128(uint32_t off) {
    return off ^ ((off >> 3) & 0x70);
}

#define CP_ASYNC16(dst, src) \
    asm volatile("cp.async.cg.shared.global [%0], [%1], 16;" :: "r"(dst), "l"(src))
#define CP_COMMIT() asm volatile("cp.async.commit_group;" ::: "memory")
#define CP_WAIT1()  asm volatile("cp.async.wait_group 1;" ::: "memory")
#define CP_WAIT0()  asm volatile("cp.async.wait_group 0;" ::: "memory")

#define LDMATRIX_X4(r0, r1, r2, r3, addr) \
    asm volatile("ldmatrix.sync.aligned.m8n8.x4.shared.b16 {%0,%1,%2,%3}, [%4];" \
                 : "=r"(r0), "=r"(r1), "=r"(r2), "=r"(r3) : "r"(addr))

#define MMA_16816(c, a, b0, b1) \
    asm volatile("mma.sync.aligned.m16n8k16.row.col.f32.bf16.bf16.f32 " \
                 "{%0,%1,%2,%3}, {%4,%5,%6,%7}, {%8,%9}, {%0,%1,%2,%3};" \
                 : "+f"((c)[0]), "+f"((c)[1]), "+f"((c)[2]), "+f"((c)[3]) \
                 : "r"((a)[0]), "r"((a)[1]), "r"((a)[2]), "r"((a)[3]), \
                   "r"(b0), "r"(b1))

// ---------------------------------------------------------------------------
// fp32 -> split bf16 conversion, 4 elems/thread (float4).
// dst row layout: [hi(512) | lo(512)].
// wmode=0 (activations): dst rows de-interleaved [B][U] -> [U][B]
// wmode=1 (weights):     dst rows unchanged
// ---------------------------------------------------------------------------
__global__ __launch_bounds__(256) void cvt_kernel(
    const float4* __restrict__ src, __nv_bfloat16* __restrict__ dst,
    int total4, int wmode)
{
    const int i = blockIdx.x * blockDim.x + threadIdx.x;   // over total/4
    if (i >= total4) return;

    const int k4  = i & 127;          // 512/4 = 128 float4 per row
    const int row = i >> 7;

    const float4 v = src[i];

    const __nv_bfloat16 hx = __float2bfloat16(v.x);
    const __nv_bfloat16 hy = __float2bfloat16(v.y);
    const __nv_bfloat16 hz = __float2bfloat16(v.z);
    const __nv_bfloat16 hw = __float2bfloat16(v.w);
    const __nv_bfloat16 lx = __float2bfloat16(v.x - __bfloat162float(hx));
    const __nv_bfloat16 ly = __float2bfloat16(v.y - __bfloat162float(hy));
    const __nv_bfloat16 lz = __float2bfloat16(v.z - __bfloat162float(hz));
    const __nv_bfloat16 lw = __float2bfloat16(v.w - __bfloat162float(hw));

    uint2 hpack, lpack;
    {
        __nv_bfloat162 h01 = __halves2bfloat162(hx, hy);
        __nv_bfloat162 h23 = __halves2bfloat162(hz, hw);
        __nv_bfloat162 l01 = __halves2bfloat162(lx, ly);
        __nv_bfloat162 l23 = __halves2bfloat162(lz, lw);
        hpack.x = *reinterpret_cast<uint32_t*>(&h01);
        hpack.y = *reinterpret_cast<uint32_t*>(&h23);
        lpack.x = *reinterpret_cast<uint32_t*>(&l01);
        lpack.y = *reinterpret_cast<uint32_t*>(&l23);
    }

    const int drow = wmode ? row : ((row & 7) * BB + (row >> 3));
    uint2* __restrict__ base = reinterpret_cast<uint2*>(dst + (size_t)drow * K2) + k4;

    base[0]   = hpack;                 // hi at k
    base[128] = lpack;                 // lo at k + 512
}

// ---------------------------------------------------------------------------
// mma.sync bf16 GEMM with split-bf16 tile reuse:
//   C = Ahi*Bhi + Alo*Bhi + Ahi*Blo
// Per K-step: load 4 tiles (Ahi, Alo, Bhi, Blo), 3 MMA passes.
// CTA tile 128x256, 8 warps (2M x 4N), warp tile 64x64.
// grid = (GN/TN=6, BB/TM=8, 16); z = u*2 + which
// ---------------------------------------------------------------------------
__global__ __launch_bounds__(256, 1) void gemm_mmasync_kernel()
{
    extern __shared__ __align__(1024) char smem[];

    const int z = blockIdx.z;
    const int u = z >> 1;
    const int w = z & 1;
    const __nv_bfloat16* __restrict__ Asrc = w ? g_hc : g_xc;
    const __nv_bfloat16* __restrict__ Wsrc = (w ? g_whh : g_wih) + (size_t)u * GN * K2;
    float* __restrict__ C = w ? g_gh : g_gx;

    const int m0 = blockIdx.y * TM;
    const int n0 = blockIdx.x * TN;

    const int tid  = threadIdx.x;
    const int wid  = tid >> 5;
    const int lane = tid & 31;
    const int wm   = wid & 1;        // warp M position (0..1)
    const int wn   = wid >> 1;       // warp N position (0..3)

    const uint32_t sb = smem_u32(smem);

    // ---------- loader precompute ----------
    const __nv_bfloat16* a_base = Asrc + ((size_t)u * BB + m0) * K2;
    const __nv_bfloat16* b_base = Wsrc + (size_t)n0 * K2;

    uint32_t a_off[4];  const __nv_bfloat16* a_src[4];
    #pragma unroll
    for (int j = 0; j < 4; ++j) {
        const int idx = tid + 256 * j;          // 0..1023
        const int r = idx >> 3, v = idx & 7;
        a_off[j] = sw128((uint32_t)(r * 128 + v * 16));
        a_src[j] = a_base + (size_t)r * K2 + v * 8;
    }
    uint32_t b_off[8];  const __nv_bfloat16* b_src[8];
    #pragma unroll
    for (int j = 0; j < 8; ++j) {
        const int idx = tid + 256 * j;          // 0..2047
        const int r = idx >> 3, v = idx & 7;
        b_off[j] = sw128((uint32_t)(r * 128 + v * 16));
        b_src[j] = b_base + (size_t)r * K2 + v * 8;
    }

    // ---------- fragment address precompute ----------
    const uint32_t a_row  = (uint32_t)(lane & 15);
    const uint32_t a_colB = (uint32_t)((lane >> 4) << 4);
    uint32_t a_frag_off[4];
    #pragma unroll
    for (int mt = 0; mt < 4; ++mt)
        a_frag_off[mt] = (uint32_t)((wm * 64 + mt * 16 + a_row) * 128) + a_colB;

    const uint32_t b_row  = (uint32_t)((lane & 7) | ((lane >> 4) << 3));
    const uint32_t b_colB = (uint32_t)(((lane >> 3) & 1) << 4);
    uint32_t b_frag_off[4];
    #pragma unroll
    for (int nb = 0; nb < 4; ++nb)
        b_frag_off[nb] = (uint32_t)((wn * 64 + nb * 16 + b_row) * 128) + b_colB;

    float acc[4][8][4];
    #pragma unroll
    for (int mt = 0; mt < 4; ++mt)
        #pragma unroll
        for (int nt = 0; nt < 8; ++nt)
            #pragma unroll
            for (int q = 0; q < 4; ++q) acc[mt][nt][q] = 0.0f;

    // ---------- stage load: 4 tiles (Ahi, Alo, Bhi, Blo) ----------
    auto load_stage = [&](int st) {
        const uint32_t base = sb + (uint32_t)st * STAGE_BYTES;
        #pragma unroll
        for (int j = 0; j < 4; ++j) {
            CP_ASYNC16(base + ST_AHI + a_off[j], a_src[j]);
            CP_ASYNC16(base + ST_ALO + a_off[j], a_src[j] + KREAL);
            a_src[j] += KC;
        }
        #pragma unroll
        for (int j = 0; j < 8; ++j) {
            CP_ASYNC16(base + ST_BHI + b_off[j], b_src[j]);
            CP_ASYNC16(base + ST_BLO + b_off[j], b_src[j] + KREAL);
            b_src[j] += KC;
        }
    };

    // prologue: stage 0
    load_stage(0);
    CP_COMMIT();

    for (int s = 0; s < NSTEPS; ++s) {
        if (s + 1 < NSTEPS) load_stage((s + 1) & 1);
        CP_COMMIT();
        CP_WAIT1();              // stage s fully loaded
        __syncthreads();

        const uint32_t base = sb + (uint32_t)(s & 1) * STAGE_BYTES;

        #pragma unroll
        for (int kk = 0; kk < 4; ++kk) {
            uint32_t ahi[4][4], bhi[4][4], tmp[4][4];

            #pragma unroll
            for (int mt = 0; mt < 4; ++mt) {
                const uint32_t addr = base + ST_AHI + sw128(a_frag_off[mt] + kk * 32);
                LDMATRIX_X4(ahi[mt][0], ahi[mt][1], ahi[mt][2], ahi[mt][3], addr);
            }
            #pragma unroll
            for (int nb = 0; nb < 4; ++nb) {
                const uint32_t addr = base + ST_BHI + sw128(b_frag_off[nb] + kk * 32);
                LDMATRIX_X4(bhi[nb][0], bhi[nb][1], bhi[nb][2], bhi[nb][3], addr);
            }
            // pass 1: Ahi * Bhi
            #pragma unroll
            for (int mt = 0; mt < 4; ++mt)
                #pragma unroll
                for (int nb = 0; nb < 4; ++nb) {
                    MMA_16816(acc[mt][2 * nb],     ahi[mt], bhi[nb][0], bhi[nb][1]);
                    MMA_16816(acc[mt][2 * nb + 1], ahi[mt], bhi[nb][2], bhi[nb][3]);
                }
            // pass 2: Alo * Bhi
            #pragma unroll
            for (int mt = 0; mt < 4; ++mt) {
                const uint32_t addr = base + ST_ALO + sw128(a_frag_off[mt] + kk * 32);
                LDMATRIX_X4(tmp[mt][0], tmp[mt][1], tmp[mt][2], tmp[mt][3], addr);
            }
            #pragma unroll
            for (int mt = 0; mt < 4; ++mt)
                #pragma unroll
                for (int nb = 0; nb < 4; ++nb) {
                    MMA_16816(acc[mt][2 * nb],     tmp[mt], bhi[nb][0], bhi[nb][1]);
                    MMA_16816(acc[mt][2 * nb + 1], tmp[mt], bhi[nb][2], bhi[nb][3]);
                }
            // pass 3: Ahi * Blo  (reuse tmp for Blo)
            #pragma unroll
            for (int nb = 0; nb < 4; ++nb) {
                const uint32_t addr = base + ST_BLO + sw128(b_frag_off[nb] + kk * 32);
                LDMATRIX_X4(tmp[nb][0], tmp[nb][1], tmp[nb][2], tmp[nb][3], addr);
            }
            #pragma unroll
            for (int mt = 0; mt < 4; ++mt)
                #pragma unroll
                for (int nb = 0; nb < 4; ++nb) {
                    MMA_16816(acc[mt][2 * nb],     ahi[mt], tmp[nb][0], tmp[nb][1]);
                    MMA_16816(acc[mt][2 * nb + 1], ahi[mt], tmp[nb][2], tmp[nb][3]);
                }
        }

        __syncthreads();        // all warps done with stage s before overwrite
    }

    // ---------- epilogue: regs -> global ([B][U][GN]) ----------
    const int g = lane >> 2;         // 0..7
    const int d = lane & 3;          // 0..3
    #pragma unroll
    for (int mt = 0; mt < 4; ++mt) {
        const int row0 = m0 + wm * 64 + mt * 16 + g;
        float* __restrict__ c0 = C + ((size_t)row0 * UU + u) * GN;
        float* __restrict__ c1 = C + ((size_t)(row0 + 8) * UU + u) * GN;
        #pragma unroll
        for (int nt = 0; nt < 8; ++nt) {
            const int col = n0 + wn * 64 + nt * 8 + d * 2;
            float2 v0 = {acc[mt][nt][0], acc[mt][nt][1]};
            float2 v1 = {acc[mt][nt][2], acc[mt][nt][3]};
            *reinterpret_cast<float2*>(c0 + col) = v0;
            *reinterpret_cast<float2*>(c1 + col) = v1;
        }
    }
}

// ---------------------------------------------------------------------------
// Elementwise GRU gates (+bias fold), 4 outputs/thread (float4)
// ---------------------------------------------------------------------------
__global__ __launch_bounds__(256) void gru_elem_kernel(
    const float4* __restrict__ Hi,    // hidden [B][U][H] as float4
    const float* __restrict__ bih,
    const float* __restrict__ bhh,
    float4* __restrict__ out)
{
    const int i = blockIdx.x * blockDim.x + threadIdx.x;   // over B*U*H/4
    if (i >= BB * UU * HH / 4) return;

    const int j4 = i & 127;          // H/4 = 128
    const int bu = i >> 7;
    const int u  = bu & (UU - 1);

    const float4* __restrict__ gx = reinterpret_cast<const float4*>(g_gx + (size_t)bu * GN) + j4;
    const float4* __restrict__ gh = reinterpret_cast<const float4*>(g_gh + (size_t)bu * GN) + j4;
    const float4* __restrict__ bi = reinterpret_cast<const float4*>(bih + u * GN) + j4;
    const float4* __restrict__ bh = reinterpret_cast<const float4*>(bhh + u * GN) + j4;

    const float4 xr = gx[0],   hr = gh[0];
    const float4 xz = gx[128], hz = gh[128];
    const float4 xn = gx[256], hn = gh[256];
    const float4 br = bi[0],   cr = bh[0];
    const float4 bz = bi[128], cz = bh[128];
    const float4 bn = bi[256], cn = bh[256];
    const float4 h  = Hi[i];

    float4 o;
    {
        const float r = 1.0f / (1.0f + __expf(-(xr.x + br.x + hr.x + cr.x)));
        const float zz = 1.0f / (1.0f + __expf(-(xz.x + bz.x + hz.x + cz.x)));
        const float n = tanhf(xn.x + bn.x + r * (hn.x + cn.x));
        o.x = (1.0f - zz) * n + zz * h.x;
    }
    {
        const float r = 1.0f / (1.0f + __expf(-(xr.y + br.y + hr.y + cr.y)));
        const float zz = 1.0f / (1.0f + __expf(-(xz.y + bz.y + hz.y + cz.y)));
        const float n = tanhf(xn.y + bn.y + r * (hn.y + cn.y));
        o.y = (1.0f - zz) * n + zz * h.y;
    }
    {
        const float r = 1.0f / (1.0f + __expf(-(xr.z + br.z + hr.z + cr.z)));
        const float zz = 1.0f / (1.0f + __expf(-(xz.z + bz.z + hz.z + cz.z)));
        const float n = tanhf(xn.z + bn.z + r * (hn.z + cn.z));
        o.z = (1.0f - zz) * n + zz * h.z;
    }
    {
        const float r = 1.0f / (1.0f + __expf(-(xr.w + br.w + hr.w + cr.w)));
        const float zz = 1.0f / (1.0f + __expf(-(xz.w + bz.w + hz.w + cz.w)));
        const float n = tanhf(xn.w + bn.w + r * (hn.w + cn.w));
        o.w = (1.0f - zz) * n + zz * h.w;
    }
    out[i] = o;
}

// ---------------------------------------------------------------------------
extern "C" void kernel_launch(void* const* d_in, const int* in_sizes, int n_in,
                              void* d_out, int out_size)
{
    const float* inputs = (const float*)d_in[0];  // [B,U,I]
    const float* hidden = (const float*)d_in[1];  // [B,U,H]
    const float* W_ih   = (const float*)d_in[2];  // [U,3H,I]
    const float* W_hh   = (const float*)d_in[3];  // [U,3H,H]
    const float* b_ih   = (const float*)d_in[4];  // [U,3H]
    const float* b_hh   = (const float*)d_in[5];  // [U,3H]
    float* out = (float*)d_out;                   // [B,U,H]

    cudaFuncSetAttribute(gemm_mmasync_kernel,
                         cudaFuncAttributeMaxDynamicSharedMemorySize, SMEM_BYTES);

    __nv_bfloat16 *xc, *hc, *wih, *whh;
    cudaGetSymbolAddress((void**)&xc,  g_xc);
    cudaGetSymbolAddress((void**)&hc,  g_hc);
    cudaGetSymbolAddress((void**)&wih, g_wih);
    cudaGetSymbolAddress((void**)&whh, g_whh);

    const int act4 = BB * UU * II / 4;      // 1,048,576
    const int w4   = UU * GN * II / 4;      // 1,572,864
    cvt_kernel<<<(act4 + 255) / 256, 256>>>((const float4*)inputs, xc,  act4, 0);
    cvt_kernel<<<(act4 + 255) / 256, 256>>>((const float4*)hidden, hc,  act4, 0);
    cvt_kernel<<<(w4   + 255) / 256, 256>>>((const float4*)W_ih,   wih, w4,   1);
    cvt_kernel<<<(w4   + 255) / 256, 256>>>((const float4*)W_hh,   whh, w4,   1);

    dim3 gemm_grid(GN / TN, BB / TM, UU * 2);   // (6, 8, 16)
    gemm_mmasync_kernel<<<gemm_grid, 256, SMEM_BYTES>>>();

    const int total4 = BB * UU * HH / 4;
    gru_elem_kernel<<<(total4 + 255) / 256, 256>>>(
        (const float4*)hidden, b_ih, b_hh, (float4*)out);
}

// round 9
// speedup vs baseline: 7.0383x; 1.3185x over previous
#include <cuda_runtime.h>
#include <cuda_bf16.h>
#include <cstdint>

// Problem constants
#define BB 1024
#define UU 8
#define II 512
#define HH 512
#define GN 1536      // 3*H

// GEMM tiling (tf32 single-pass)
#define TM 128
#define TN 256
#define KC 32                 // fp32 k per stage (128 B rows)
#define NSTEPS (II / KC)      // 16
#define STAGES 4
#define ST_B (TM * 128)                       // A: 16 KB, then B: 32 KB
#define STAGE_BYTES (TM * 128 + TN * 128)     // 48 KB
#define SMEM_BYTES (STAGES * STAGE_BYTES)     // 192 KB

// ---------------------------------------------------------------------------
// Device scratch: only the GEMM outputs
// ---------------------------------------------------------------------------
__device__ float g_gx[(size_t)BB * UU * GN];             // [B][U][GN]
__device__ float g_gh[(size_t)BB * UU * GN];

// ---------------------------------------------------------------------------
// helpers
// ---------------------------------------------------------------------------
__device__ __forceinline__ uint32_t smem_u32(const void* p) {
    return (uint32_t)__cvta_generic_to_shared(p);
}
__device__ __forceinline__ uint32_t sw128(uint32_t off) {
    return off ^ ((off >> 3) & 0x70);
}

#define CP_ASYNC16(dst, src) \
    asm volatile("cp.async.cg.shared.global [%0], [%1], 16;" :: "r"(dst), "l"(src))
#define CP_COMMIT() asm volatile("cp.async.commit_group;" ::: "memory")
#define CP_WAIT2()  asm volatile("cp.async.wait_group 2;" ::: "memory")

#define LDMATRIX_X4(r0, r1, r2, r3, addr) \
    asm volatile("ldmatrix.sync.aligned.m8n8.x4.shared.b16 {%0,%1,%2,%3}, [%4];" \
                 : "=r"(r0), "=r"(r1), "=r"(r2), "=r"(r3) : "r"(addr))

// round-to-nearest f32 -> tf32 (keeps value in b32 reg, low mantissa zeroed)
#define CVT_TF32(r) asm volatile("cvt.rna.tf32.f32 %0, %0;" : "+r"(r))

#define MMA_TF32(c, a0, a1, a2, a3, b0, b1) \
    asm volatile("mma.sync.aligned.m16n8k8.row.col.f32.tf32.tf32.f32 " \
                 "{%0,%1,%2,%3}, {%4,%5,%6,%7}, {%8,%9}, {%0,%1,%2,%3};" \
                 : "+f"((c)[0]), "+f"((c)[1]), "+f"((c)[2]), "+f"((c)[3]) \
                 : "r"(a0), "r"(a1), "r"(a2), "r"(a3), "r"(b0), "r"(b1))

// ---------------------------------------------------------------------------
// tf32 mma.sync GEMM, reading raw fp32 inputs directly:
//   C[b, u, g] = sum_k A[b, u, k] * W[u, g, k]
// CTA tile 128x256, 8 warps (2M x 4N), warp tile 64x64.
// grid = (GN/TN=6, BB/TM=8, 16); z = u*2 + which
// ---------------------------------------------------------------------------
__global__ __launch_bounds__(256, 1) void gemm_tf32_kernel(
    const float* __restrict__ X,    // inputs  [B,U,I]
    const float* __restrict__ Hi,   // hidden  [B,U,H]
    const float* __restrict__ Wih,  // [U,GN,I]
    const float* __restrict__ Whh)  // [U,GN,H]
{
    extern __shared__ __align__(1024) char smem[];

    const int z = blockIdx.z;
    const int u = z >> 1;
    const int w = z & 1;
    const float* __restrict__ Asrc = w ? Hi : X;
    const float* __restrict__ Wsrc = (w ? Whh : Wih) + (size_t)u * GN * II;
    float* __restrict__ C = w ? g_gh : g_gx;

    const int m0 = blockIdx.y * TM;
    const int n0 = blockIdx.x * TN;

    const int tid  = threadIdx.x;
    const int wid  = tid >> 5;
    const int lane = tid & 31;
    const int wm   = wid & 1;        // warp M position (0..1)
    const int wn   = wid >> 1;       // warp N position (0..3)

    const uint32_t sb = smem_u32(smem);

    // ---------- loader precompute ----------
    // A tile: 128 rows x 128 B (32 fp32). Original layout: row b at (b*UU+u)*II.
    uint32_t a_off[4];  const float* a_src[4];
    #pragma unroll
    for (int j = 0; j < 4; ++j) {
        const int idx = tid + 256 * j;          // 0..1023
        const int r = idx >> 3, v = idx & 7;
        a_off[j] = sw128((uint32_t)(r * 128 + v * 16));
        a_src[j] = Asrc + ((size_t)(m0 + r) * UU + u) * II + v * 4;
    }
    // B tile: 256 rows x 128 B. Row g at g*II (contiguous).
    uint32_t b_off[8];  const float* b_src[8];
    #pragma unroll
    for (int j = 0; j < 8; ++j) {
        const int idx = tid + 256 * j;          // 0..2047
        const int r = idx >> 3, v = idx & 7;
        b_off[j] = sw128((uint32_t)(r * 128 + v * 16));
        b_src[j] = Wsrc + (size_t)(n0 + r) * II + v * 4;
    }

    // ---------- fragment address precompute (tf32 via b16 ldmatrix) ----------
    // A x4 per (mt, kk): groups g0:(m0-7,k0-3) g1:(m8-15,k0-3) g2:(m0-7,k4-7) g3:(m8-15,k4-7)
    const uint32_t a_row  = (uint32_t)((lane & 7) + ((lane >> 3) & 1) * 8);
    const uint32_t a_colB = (uint32_t)((lane >> 4) << 4);
    uint32_t a_frag_off[4];
    #pragma unroll
    for (int mt = 0; mt < 4; ++mt)
        a_frag_off[mt] = (uint32_t)((wm * 64 + mt * 16 + a_row) * 128) + a_colB;

    // B x4 per (nb, kk): groups g0:(n0-7,k0-3) g1:(n0-7,k4-7) g2:(n8-15,k0-3) g3:(n8-15,k4-7)
    const uint32_t b_row  = (uint32_t)((lane & 7) + ((lane >> 4) & 1) * 8);
    const uint32_t b_colB = (uint32_t)(((lane >> 3) & 1) << 4);
    uint32_t b_frag_off[4];
    #pragma unroll
    for (int nb = 0; nb < 4; ++nb)
        b_frag_off[nb] = (uint32_t)((wn * 64 + nb * 16 + b_row) * 128) + b_colB;

    float acc[4][8][4];
    #pragma unroll
    for (int mt = 0; mt < 4; ++mt)
        #pragma unroll
        for (int nt = 0; nt < 8; ++nt)
            #pragma unroll
            for (int q = 0; q < 4; ++q) acc[mt][nt][q] = 0.0f;

    // ---------- stage load ----------
    auto load_stage = [&](int st) {
        const uint32_t abase = sb + (uint32_t)st * STAGE_BYTES;
        const uint32_t bbase = abase + ST_B;
        #pragma unroll
        for (int j = 0; j < 4; ++j) {
            CP_ASYNC16(abase + a_off[j], a_src[j]);
            a_src[j] += KC;
        }
        #pragma unroll
        for (int j = 0; j < 8; ++j) {
            CP_ASYNC16(bbase + b_off[j], b_src[j]);
            b_src[j] += KC;
        }
    };

    // prologue: stages 0..2
    #pragma unroll
    for (int p = 0; p < STAGES - 1; ++p) { load_stage(p); CP_COMMIT(); }

    for (int s = 0; s < NSTEPS; ++s) {
        CP_WAIT2();              // stage s ready (2 newest groups may be pending)
        __syncthreads();         // all warps done with stage s-1 -> safe to refill

        if (s + STAGES - 1 < NSTEPS) load_stage((s + STAGES - 1) & (STAGES - 1));
        CP_COMMIT();             // commit every iter (possibly empty) to keep counts

        const uint32_t As = sb + (uint32_t)(s & (STAGES - 1)) * STAGE_BYTES;
        const uint32_t Bs = As + ST_B;

        #pragma unroll
        for (int kk = 0; kk < 4; ++kk) {        // 4 x k8 within KC=32
            uint32_t a[4][4], b[4][4];
            #pragma unroll
            for (int mt = 0; mt < 4; ++mt) {
                const uint32_t addr = As + sw128(a_frag_off[mt] + kk * 32);
                LDMATRIX_X4(a[mt][0], a[mt][1], a[mt][2], a[mt][3], addr);
                CVT_TF32(a[mt][0]); CVT_TF32(a[mt][1]);
                CVT_TF32(a[mt][2]); CVT_TF32(a[mt][3]);
            }
            #pragma unroll
            for (int nb = 0; nb < 4; ++nb) {
                const uint32_t addr = Bs + sw128(b_frag_off[nb] + kk * 32);
                LDMATRIX_X4(b[nb][0], b[nb][1], b[nb][2], b[nb][3], addr);
                CVT_TF32(b[nb][0]); CVT_TF32(b[nb][1]);
                CVT_TF32(b[nb][2]); CVT_TF32(b[nb][3]);
            }
            #pragma unroll
            for (int mt = 0; mt < 4; ++mt) {
                #pragma unroll
                for (int nb = 0; nb < 4; ++nb) {
                    MMA_TF32(acc[mt][2 * nb],
                             a[mt][0], a[mt][1], a[mt][2], a[mt][3],
                             b[nb][0], b[nb][1]);
                    MMA_TF32(acc[mt][2 * nb + 1],
                             a[mt][0], a[mt][1], a[mt][2], a[mt][3],
                             b[nb][2], b[nb][3]);
                }
            }
        }
    }

    // ---------- epilogue: regs -> global ([B][U][GN]) ----------
    const int g = lane >> 2;         // 0..7
    const int d = lane & 3;          // 0..3
    #pragma unroll
    for (int mt = 0; mt < 4; ++mt) {
        const int row0 = m0 + wm * 64 + mt * 16 + g;
        float* __restrict__ c0 = C + ((size_t)row0 * UU + u) * GN;
        float* __restrict__ c1 = C + ((size_t)(row0 + 8) * UU + u) * GN;
        #pragma unroll
        for (int nt = 0; nt < 8; ++nt) {
            const int col = n0 + wn * 64 + nt * 8 + d * 2;
            float2 v0 = {acc[mt][nt][0], acc[mt][nt][1]};
            float2 v1 = {acc[mt][nt][2], acc[mt][nt][3]};
            *reinterpret_cast<float2*>(c0 + col) = v0;
            *reinterpret_cast<float2*>(c1 + col) = v1;
        }
    }
}

// ---------------------------------------------------------------------------
// Elementwise GRU gates (+bias fold), 4 outputs/thread (float4)
// ---------------------------------------------------------------------------
__global__ __launch_bounds__(256) void gru_elem_kernel(
    const float4* __restrict__ Hi,    // hidden [B][U][H] as float4
    const float* __restrict__ bih,
    const float* __restrict__ bhh,
    float4* __restrict__ out)
{
    const int i = blockIdx.x * blockDim.x + threadIdx.x;   // over B*U*H/4
    if (i >= BB * UU * HH / 4) return;

    const int j4 = i & 127;          // H/4 = 128
    const int bu = i >> 7;
    const int u  = bu & (UU - 1);

    const float4* __restrict__ gx = reinterpret_cast<const float4*>(g_gx + (size_t)bu * GN) + j4;
    const float4* __restrict__ gh = reinterpret_cast<const float4*>(g_gh + (size_t)bu * GN) + j4;
    const float4* __restrict__ bi = reinterpret_cast<const float4*>(bih + u * GN) + j4;
    const float4* __restrict__ bh = reinterpret_cast<const float4*>(bhh + u * GN) + j4;

    const float4 xr = gx[0],   hr = gh[0];
    const float4 xz = gx[128], hz = gh[128];
    const float4 xn = gx[256], hn = gh[256];
    const float4 br = bi[0],   cr = bh[0];
    const float4 bz = bi[128], cz = bh[128];
    const float4 bn = bi[256], cn = bh[256];
    const float4 h  = Hi[i];

    float4 o;
    {
        const float r = 1.0f / (1.0f + __expf(-(xr.x + br.x + hr.x + cr.x)));
        const float zz = 1.0f / (1.0f + __expf(-(xz.x + bz.x + hz.x + cz.x)));
        const float n = tanhf(xn.x + bn.x + r * (hn.x + cn.x));
        o.x = (1.0f - zz) * n + zz * h.x;
    }
    {
        const float r = 1.0f / (1.0f + __expf(-(xr.y + br.y + hr.y + cr.y)));
        const float zz = 1.0f / (1.0f + __expf(-(xz.y + bz.y + hz.y + cz.y)));
        const float n = tanhf(xn.y + bn.y + r * (hn.y + cn.y));
        o.y = (1.0f - zz) * n + zz * h.y;
    }
    {
        const float r = 1.0f / (1.0f + __expf(-(xr.z + br.z + hr.z + cr.z)));
        const float zz = 1.0f / (1.0f + __expf(-(xz.z + bz.z + hz.z + cz.z)));
        const float n = tanhf(xn.z + bn.z + r * (hn.z + cn.z));
        o.z = (1.0f - zz) * n + zz * h.z;
    }
    {
        const float r = 1.0f / (1.0f + __expf(-(xr.w + br.w + hr.w + cr.w)));
        const float zz = 1.0f / (1.0f + __expf(-(xz.w + bz.w + hz.w + cz.w)));
        const float n = tanhf(xn.w + bn.w + r * (hn.w + cn.w));
        o.w = (1.0f - zz) * n + zz * h.w;
    }
    out[i] = o;
}

// ---------------------------------------------------------------------------
extern "C" void kernel_launch(void* const* d_in, const int* in_sizes, int n_in,
                              void* d_out, int out_size)
{
    const float* inputs = (const float*)d_in[0];  // [B,U,I]
    const float* hidden = (const float*)d_in[1];  // [B,U,H]
    const float* W_ih   = (const float*)d_in[2];  // [U,3H,I]
    const float* W_hh   = (const float*)d_in[3];  // [U,3H,H]
    const float* b_ih   = (const float*)d_in[4];  // [U,3H]
    const float* b_hh   = (const float*)d_in[5];  // [U,3H]
    float* out = (float*)d_out;                   // [B,U,H]

    cudaFuncSetAttribute(gemm_tf32_kernel,
                         cudaFuncAttributeMaxDynamicSharedMemorySize, SMEM_BYTES);

    dim3 gemm_grid(GN / TN, BB / TM, UU * 2);   // (6, 8, 16)
    gemm_tf32_kernel<<<gemm_grid, 256, SMEM_BYTES>>>(inputs, hidden, W_ih, W_hh);

    const int total4 = BB * UU * HH / 4;
    gru_elem_kernel<<<(total4 + 255) / 256, 256>>>(
        (const float4*)hidden, b_ih, b_hh, (float4*)out);
}